// round 2
// baseline (speedup 1.0000x reference)
#include <cuda_runtime.h>

#define B_      2048
#define T_      500
#define N_      64
#define CHUNK_T 10
#define NCHUNK  (T_ / CHUNK_T)        // 50
#define NBLK    148                   // one full wave on B200 (148 SMs)
#define SCANB   32                    // scan blocks (warps 0-3 active)
#define ROWB    (NBLK - SCANB)        // 116 producer blocks
#define ROWW    (ROWB * 8)            // 928 producer warps

// Rowsum scratch [T][B], padded so the scan prefetch can read past T unguarded.
__device__ float    g_S[(T_ + 12) * B_];
__device__ unsigned g_cnt[NCHUNK];

__global__ void init_kernel() {
    if (threadIdx.x < NCHUNK) g_cnt[threadIdx.x] = 0u;
}

__device__ __forceinline__ unsigned ld_acquire(const unsigned* p) {
    unsigned v;
    asm volatile("ld.acquire.gpu.u32 %0, [%1];" : "=r"(v) : "l"(p));
    return v;
}

// ---------------------------------------------------------------------------
// Izhikevich pieces (DT=0.25, V_TH=30).
// partial = v + 0.25*(v*(0.04v+5) + 140 - u)  -- independent of this step's I,
// so the spike cascade only pays one fma + compare + select per neuron.
// ---------------------------------------------------------------------------
__device__ __forceinline__ float izh_partial(float v, float u) {
    float p = fmaf(0.04f, v, 5.0f);
    float q = fmaf(v, p, 140.0f - u);
    return fmaf(0.25f, q, v);
}

// vn = partial + 0.25*I already folded in by caller. Updates v,u; returns z.
__device__ __forceinline__ float izh_core(float& v, float& u, float vn,
                                          float bb, float c, float d) {
    bool  sp = (vn >= 30.0f);
    float z  = sp ? 1.0f : 0.0f;
    float ug = fmaf(bb, v, -u);          // uses OLD v
    float un = fmaf(0.005f, ug, u);      // 0.25 * a, a = 0.02 for all cells
    v = sp ? c : vn;
    u = fmaf(d, z, un);
    return z;
}

// ---------------------------------------------------------------------------
// Fused persistent kernel: producer blocks stream rowsums chunk-by-chunk,
// scan blocks consume with acquire-polling. All 148 blocks co-resident.
// ---------------------------------------------------------------------------
__global__ void __launch_bounds__(256, 1)
fused_kernel(const float* __restrict__ in, const float* __restrict__ w,
             float* __restrict__ out) {
    const int wid  = threadIdx.x >> 5;
    const int lane = threadIdx.x & 31;

    if (blockIdx.x >= SCANB) {
        // ================= producer: rowsum in chunks of 10 timesteps ======
        const int rw = (blockIdx.x - SCANB) * 8 + wid;   // 0..927
        for (int c = 0; c < NCHUNK; ++c) {
            const int t0 = c * CHUNK_T;
            for (int b = rw; b < B_; b += ROWW) {
                const float2* p = reinterpret_cast<const float2*>(in)
                                + ((size_t)b * T_ + t0) * 32 + lane;
                float s[CHUNK_T];
                #pragma unroll
                for (int j = 0; j < CHUNK_T; ++j) {      // 10 loads in flight
                    float2 x = p[j * 32];
                    s[j] = x.x + x.y;
                }
                #pragma unroll
                for (int j = 0; j < CHUNK_T; ++j)
                    #pragma unroll
                    for (int o = 16; o; o >>= 1)
                        s[j] += __shfl_xor_sync(0xffffffffu, s[j], o);
                if (lane == 0) {
                    #pragma unroll
                    for (int j = 0; j < CHUNK_T; ++j)
                        g_S[(t0 + j) * B_ + b] = s[j];
                }
            }
            __syncthreads();                              // block's chunk done
            if (threadIdx.x == 0) {
                __threadfence();                          // release S stores
                atomicAdd(&g_cnt[c], 1u);
            }
        }
        return;
    }

    // ==================== consumer: the T=500 scan =========================
    if (wid >= 4) return;                      // one scan warp per SMSP
    const int swid = blockIdx.x * 4 + wid;     // 0..127
    const int ch   = swid & 1;                 // 0 = channel 1, 1 = channel 2
    const int b    = (swid >> 1) * 32 + lane;  // batch index

    // Fold weights into 0.25-scaled input coefficients.
    float QCL, QCE, QWE, QWI, QCT, QWM;
    if (ch == 0) {
        QCL = 0.25f * (w[2] * (w[0] * w[1]));
        QCE = 0.25f * (w[0] * w[4]);
        QWE = 0.25f * w[5];
        QWI = 0.25f * w[6];
        QCT = 0.25f * (w[9] * w[8]);
        QWM = 0.25f * w[11];
    } else {
        QCL = 0.25f * (w[2] * (w[12] * w[13]));
        QCE = 0.25f * (w[12] * w[16]);
        QWE = 0.25f * w[17];
        QWI = 0.25f * w[18];
        QCT = 0.25f * (w[9] * w[20]);
        QWM = 0.25f * w[23];
    }
    const float QW3  = 0.25f * w[3];
    const float QW10 = 0.25f * w[10];

    float vL = -70.f, uL = -14.f, zL = 0.f;    // LLBN (b=.20,c=-65,d=6)
    float vE = -64.f, uE = -16.f;              // EBN  (b=.25,c=-55,d=.05)
    float vI = -64.f, uI = -16.f;              // IFN  (b=.25,c=-65,d=6)
    float vT = -70.f, uT = -14.f, zT = 0.f;    // TN   (b=.20,c=-50,d=2)
    float vM = -64.f, uM = -16.f;              // MN = IFN

    const size_t BT = (size_t)B_ * T_;
    float*  out_sA = out + (ch ? 2 * BT : 0)      + (size_t)b * T_;  // z6/z62
    float*  out_sB = out + (ch ? 3 * BT : 1 * BT) + (size_t)b * T_;  // vM/vM2
    float4* out_o4 = reinterpret_cast<float4*>(out + 4 * BT) + (size_t)b * T_;
    float4* out_v4 = reinterpret_cast<float4*>(out + 8 * BT) + (size_t)b * T_;

    int hc = -1;                               // highest chunk seen complete
    // wait for chunk 0, then preload first 4 timesteps
    while (ld_acquire(&g_cnt[0]) < (unsigned)ROWB) __nanosleep(64);
    hc = 0;

    float cur[4], nxt[4];
    #pragma unroll
    for (int j = 0; j < 4; j++) cur[j] = g_S[j * B_ + b];

    for (int t4 = 0; t4 < T_; t4 += 4) {
        int req = (t4 + 7) / CHUNK_T;
        if (req > NCHUNK - 1) req = NCHUNK - 1;
        if (req > hc) {                        // monotonic: at most one poll/chunk
            while (ld_acquire(&g_cnt[req]) < (unsigned)ROWB) __nanosleep(64);
            hc = req;
        }
        #pragma unroll
        for (int j = 0; j < 4; j++) nxt[j] = g_S[(t4 + 4 + j) * B_ + b];

        float z6s[4], vMs[4];
        #pragma unroll
        for (int j = 0; j < 4; j++) {
            const float S = cur[j];

            // partials: independent of this step's spikes -> full ILP
            float pL = izh_partial(vL, uL);
            float pE = izh_partial(vE, uE);
            float pI = izh_partial(vI, uI);
            float pT = izh_partial(vT, uT);
            float pM = izh_partial(vM, uM);

            float vnL = fmaf(QW3, zL, fmaf(QCL, S, pL));
            float z2  = izh_core(vL, uL, vnL, 0.20f, -65.f, 6.f);
            zL = z2;

            float vnE = fmaf(QWE, z2, fmaf(QCE, S, pE));
            float z3  = izh_core(vE, uE, vnE, 0.25f, -55.f, 0.05f);

            float vnI = fmaf(QWI, z3, pI);
            float z4  = izh_core(vI, uI, vnI, 0.25f, -65.f, 6.f);

            float vnT = fmaf(QCT, z3, fmaf(QW10, zT, pT));
            float z5  = izh_core(vT, uT, vnT, 0.20f, -50.f, 2.f);
            zT = z5;

            float vnM = fmaf(QWM, z5, pM);
            float z6  = izh_core(vM, uM, vnM, 0.25f, -65.f, 6.f);

            z6s[j] = z6;
            vMs[j] = vM;

            if (ch == 0) {                     // channel-1 warp emits 4-wide streams
                out_o4[t4 + j] = make_float4(z2, z3, z4, z5);
                out_v4[t4 + j] = make_float4(vL, vE, vI, vT);
            }
        }

        *reinterpret_cast<float4*>(out_sA + t4) =
            make_float4(z6s[0], z6s[1], z6s[2], z6s[3]);
        *reinterpret_cast<float4*>(out_sB + t4) =
            make_float4(vMs[0], vMs[1], vMs[2], vMs[3]);

        #pragma unroll
        for (int j = 0; j < 4; j++) cur[j] = nxt[j];
    }
}

// ---------------------------------------------------------------------------
extern "C" void kernel_launch(void* const* d_in, const int* in_sizes, int n_in,
                              void* d_out, int out_size) {
    const float* inp = (const float*)d_in[0];
    const float* w   = (const float*)d_in[1];
    if (in_sizes[0] == 24) { const float* t = inp; inp = w; w = t; }

    init_kernel<<<1, 64>>>();
    fused_kernel<<<NBLK, 256>>>(inp, w, (float*)d_out);
}

// round 3
// speedup vs baseline: 1.0870x; 1.0870x over previous
#include <cuda_runtime.h>

#define B_      2048
#define T_      500
#define N_      64
#define CHUNK_T 20
#define NCHUNK  (T_ / CHUNK_T)        // 25
#define NBLK    148                   // one full wave on B200
#define TPB     512
#define SCANB   32                    // blocks whose warps 0-3 run the scan
#define PRODW   (SCANB * 12 + (NBLK - SCANB) * 16)   // 2240 producer warps

// Rowsum scratch [T][B], padded so scan prefetch can read past T unguarded.
__device__ float    g_S[(T_ + 12) * B_];
__device__ unsigned g_cnt[NCHUNK];

__global__ void init_kernel() {
    if (threadIdx.x < NCHUNK) g_cnt[threadIdx.x] = 0u;
}

__device__ __forceinline__ unsigned ld_acquire(const unsigned* p) {
    unsigned v;
    asm volatile("ld.acquire.gpu.u32 %0, [%1];" : "=r"(v) : "l"(p));
    return v;
}

// ---------------------------------------------------------------------------
// Izhikevich pieces (DT=0.25, V_TH=30).
// partial = v + 0.25*(v*(0.04v+5) + 140 - u): independent of this step's I,
// so each cascade edge costs only fma -> setp -> sel.
// ---------------------------------------------------------------------------
__device__ __forceinline__ float izh_partial(float v, float u) {
    float p = fmaf(0.04f, v, 5.0f);
    float q = fmaf(v, p, 140.0f - u);
    return fmaf(0.25f, q, v);
}

__device__ __forceinline__ float izh_core(float& v, float& u, float vn,
                                          float bb, float c, float d) {
    bool  sp = (vn >= 30.0f);
    float z  = sp ? 1.0f : 0.0f;
    float ug = fmaf(bb, v, -u);          // uses OLD v
    float un = fmaf(0.005f, ug, u);      // 0.25 * a, a = 0.02 for all cells
    v = sp ? c : vn;
    u = fmaf(d, z, un);
    return z;
}

// ---------------------------------------------------------------------------
// Fused persistent kernel. 148 blocks x 512 threads, all co-resident.
//   blocks 0-31, warps 0-3   : scan (128 warps = 2048 batches x 2 channels)
//   all other warps (2240)   : producers; one batch per warp per chunk.
// ---------------------------------------------------------------------------
__global__ void __launch_bounds__(TPB, 1)
fused_kernel(const float* __restrict__ in, const float* __restrict__ w,
             float* __restrict__ out) {
    const int wid  = threadIdx.x >> 5;
    const int lane = threadIdx.x & 31;
    const bool scan_block = (blockIdx.x < SCANB);

    if (!(scan_block && wid < 4)) {
        // ===================== producer =====================
        const int pw = scan_block ? (blockIdx.x * 12 + (wid - 4))
                                  : (SCANB * 12 + (blockIdx.x - SCANB) * 16 + wid);
        const int b    = pw;                     // one batch per warp (pw<B_)
        const int half = lane >> 4;              // 0/1: which of 2 rows per round
        const int col  = lane & 15;              // float4 slot within row

        for (int c = 0; c < NCHUNK; ++c) {
            if (b < B_) {
                const int t0 = c * CHUNK_T;
                const float4* base = reinterpret_cast<const float4*>(in)
                                   + ((size_t)b * T_ + t0 + half) * 16 + col;
                float4 x[10];
                #pragma unroll
                for (int r = 0; r < 10; ++r)     // 10 x LDG.128 in flight
                    x[r] = base[r * 32];         // 2 rows per round

                #pragma unroll
                for (int r = 0; r < 10; ++r) {
                    float s = (x[r].x + x[r].y) + (x[r].z + x[r].w);
                    #pragma unroll
                    for (int o = 8; o; o >>= 1)  // reduce within 16-lane half
                        s += __shfl_xor_sync(0xffffffffu, s, o);
                    if (col == 0)                // lanes 0 and 16 hold row sums
                        g_S[(t0 + 2 * r + half) * B_ + b] = s;
                }
            }
            __syncwarp();
            if (lane == 0) {
                __threadfence();                 // release S stores (cumulative)
                atomicAdd(&g_cnt[c], 1u);
            }
        }
        return;
    }

    // ===================== scan =====================
    const int swid = blockIdx.x * 4 + wid;       // 0..127
    const int ch   = swid & 1;                   // 0 = channel 1, 1 = channel 2
    const int b    = (swid >> 1) * 32 + lane;    // batch index

    float QCL, QCE, QWE, QWI, QCT, QWM;
    if (ch == 0) {
        QCL = 0.25f * (w[2] * (w[0] * w[1]));
        QCE = 0.25f * (w[0] * w[4]);
        QWE = 0.25f * w[5];
        QWI = 0.25f * w[6];
        QCT = 0.25f * (w[9] * w[8]);
        QWM = 0.25f * w[11];
    } else {
        QCL = 0.25f * (w[2] * (w[12] * w[13]));
        QCE = 0.25f * (w[12] * w[16]);
        QWE = 0.25f * w[17];
        QWI = 0.25f * w[18];
        QCT = 0.25f * (w[9] * w[20]);
        QWM = 0.25f * w[23];
    }
    const float QW3  = 0.25f * w[3];
    const float QW10 = 0.25f * w[10];

    float vL = -70.f, uL = -14.f, zL = 0.f;      // LLBN (b=.20,c=-65,d=6)
    float vE = -64.f, uE = -16.f;                // EBN  (b=.25,c=-55,d=.05)
    float vI = -64.f, uI = -16.f;                // IFN  (b=.25,c=-65,d=6)
    float vT = -70.f, uT = -14.f, zT = 0.f;      // TN   (b=.20,c=-50,d=2)
    float vM = -64.f, uM = -16.f;                // MN = IFN

    const size_t BT = (size_t)B_ * T_;
    float*  out_sA = out + (ch ? 2 * BT : 0)      + (size_t)b * T_;  // z6/z62
    float*  out_sB = out + (ch ? 3 * BT : 1 * BT) + (size_t)b * T_;  // vM/vM2
    float4* out_o4 = reinterpret_cast<float4*>(out + 4 * BT) + (size_t)b * T_;
    float4* out_v4 = reinterpret_cast<float4*>(out + 8 * BT) + (size_t)b * T_;

    while (ld_acquire(&g_cnt[0]) < (unsigned)PRODW) __nanosleep(64);
    int hc = 0;

    float cur[4], nxt[4];
    #pragma unroll
    for (int j = 0; j < 4; j++) cur[j] = g_S[j * B_ + b];

    for (int t4 = 0; t4 < T_; t4 += 4) {
        int req = (t4 + 7) / CHUNK_T;
        if (req > NCHUNK - 1) req = NCHUNK - 1;
        if (req > hc) {                          // at most one poll per chunk
            while (ld_acquire(&g_cnt[req]) < (unsigned)PRODW) __nanosleep(64);
            hc = req;
        }
        #pragma unroll
        for (int j = 0; j < 4; j++) nxt[j] = g_S[(t4 + 4 + j) * B_ + b];

        float z6s[4], vMs[4];
        #pragma unroll
        for (int j = 0; j < 4; j++) {
            const float S = cur[j];

            float pL = izh_partial(vL, uL);
            float pE = izh_partial(vE, uE);
            float pI = izh_partial(vI, uI);
            float pT = izh_partial(vT, uT);
            float pM = izh_partial(vM, uM);

            float vnL = fmaf(QW3, zL, fmaf(QCL, S, pL));
            float z2  = izh_core(vL, uL, vnL, 0.20f, -65.f, 6.f);
            zL = z2;

            float vnE = fmaf(QWE, z2, fmaf(QCE, S, pE));
            float z3  = izh_core(vE, uE, vnE, 0.25f, -55.f, 0.05f);

            float vnI = fmaf(QWI, z3, pI);
            float z4  = izh_core(vI, uI, vnI, 0.25f, -65.f, 6.f);

            float vnT = fmaf(QCT, z3, fmaf(QW10, zT, pT));
            float z5  = izh_core(vT, uT, vnT, 0.20f, -50.f, 2.f);
            zT = z5;

            float vnM = fmaf(QWM, z5, pM);
            float z6  = izh_core(vM, uM, vnM, 0.25f, -65.f, 6.f);

            z6s[j] = z6;
            vMs[j] = vM;

            if (ch == 0) {                       // channel-1 warp emits 4-wide streams
                out_o4[t4 + j] = make_float4(z2, z3, z4, z5);
                out_v4[t4 + j] = make_float4(vL, vE, vI, vT);
            }
        }

        *reinterpret_cast<float4*>(out_sA + t4) =
            make_float4(z6s[0], z6s[1], z6s[2], z6s[3]);
        *reinterpret_cast<float4*>(out_sB + t4) =
            make_float4(vMs[0], vMs[1], vMs[2], vMs[3]);

        #pragma unroll
        for (int j = 0; j < 4; j++) cur[j] = nxt[j];
    }
}

// ---------------------------------------------------------------------------
extern "C" void kernel_launch(void* const* d_in, const int* in_sizes, int n_in,
                              void* d_out, int out_size) {
    const float* inp = (const float*)d_in[0];
    const float* w   = (const float*)d_in[1];
    if (in_sizes[0] == 24) { const float* t = inp; inp = w; w = t; }

    init_kernel<<<1, 32>>>();
    fused_kernel<<<NBLK, TPB>>>(inp, w, (float*)d_out);
}

// round 5
// speedup vs baseline: 1.7259x; 1.5877x over previous
#include <cuda_runtime.h>

#define B_      2048
#define T_      500
#define N_      64
#define CHUNK_T 20
#define NCHUNK  (T_ / CHUNK_T)        // 25
#define NBLK    148                   // one full wave
#define TPB     512
#define SCANB   32                    // blocks whose warps 0-3 run the scan

// Rowsum scratch [T][B], padded so scan prefetch (8 ahead) reads past T safely.
__device__ float    g_S[(T_ + 16) * B_];
// One counter per 128B line so the 25 chunk counters hit different LTS slices.
__device__ unsigned g_cnt[NCHUNK * 32];

__global__ void init_kernel() {
    if (threadIdx.x < NCHUNK * 32) g_cnt[threadIdx.x] = 0u;
}

__device__ __forceinline__ unsigned ld_acquire(const unsigned* p) {
    unsigned v;
    asm volatile("ld.acquire.gpu.u32 %0, [%1];" : "=r"(v) : "l"(p));
    return v;
}

// ---------------------------------------------------------------------------
// Izhikevich pieces (DT=0.25, V_TH=30).
// partial = v + 0.25*(v*(0.04v+5) + 140 - u): independent of this step's I,
// so each cascade edge costs only fma -> setp -> sel.
// ---------------------------------------------------------------------------
__device__ __forceinline__ float izh_partial(float v, float u) {
    float p = fmaf(0.04f, v, 5.0f);
    float q = fmaf(v, p, 140.0f - u);
    return fmaf(0.25f, q, v);
}

__device__ __forceinline__ float izh_core(float& v, float& u, float vn,
                                          float bb, float c, float d) {
    bool  sp = (vn >= 30.0f);
    float z  = sp ? 1.0f : 0.0f;
    float ug = fmaf(bb, v, -u);          // uses OLD v
    float un = fmaf(0.005f, ug, u);      // 0.25 * a, a = 0.02 for all cells
    v = sp ? c : vn;
    u = fmaf(d, z, un);
    return z;
}

// ---------------------------------------------------------------------------
// Fused persistent kernel. 148 blocks x 512 threads, all co-resident.
//   blocks 0-31, warps 0-3 : scan (128 warps = 2048 batches x 2 channels)
//   all other warps        : producers; one batch per warp per chunk.
// Release protocol: ONE fence+atomicAdd per block per chunk (barrier first).
// ---------------------------------------------------------------------------
__global__ void __launch_bounds__(TPB, 1)
fused_kernel(const float* __restrict__ in, const float* __restrict__ w,
             float* __restrict__ out) {
    const int wid  = threadIdx.x >> 5;
    const int lane = threadIdx.x & 31;
    const bool scan_block = (blockIdx.x < SCANB);

    if (!(scan_block && wid < 4)) {
        // ===================== producer =====================
        const int b = scan_block ? (blockIdx.x * 12 + (wid - 4))
                                 : (SCANB * 12 + (blockIdx.x - SCANB) * 16 + wid);
        const int half = lane >> 4;              // which of 2 rows per round
        const int col  = lane & 15;              // float4 slot within row

        for (int c = 0; c < NCHUNK; ++c) {
            if (b < B_) {
                const int t0 = c * CHUNK_T;
                const float4* base = reinterpret_cast<const float4*>(in)
                                   + ((size_t)b * T_ + t0 + half) * 16 + col;
                float4 x[10];
                #pragma unroll
                for (int r = 0; r < 10; ++r)     // 10 x LDG.128 in flight
                    x[r] = base[r * 32];         // 2 rows per round

                #pragma unroll
                for (int r = 0; r < 10; ++r) {
                    float s = (x[r].x + x[r].y) + (x[r].z + x[r].w);
                    #pragma unroll
                    for (int o = 8; o; o >>= 1)  // reduce within 16-lane half
                        s += __shfl_xor_sync(0xffffffffu, s, o);
                    if (col == 0)                // lanes 0 / 16 hold row sums
                        g_S[(t0 + 2 * r + half) * B_ + b] = s;
                }
            }
            // Block-granular release: barrier gives CTA-scope visibility of
            // all the block's S stores; one fence+atomic publishes them.
            if (scan_block) {
                asm volatile("bar.sync 1, %0;" :: "n"(12 * 32) : "memory");
                if (wid == 4 && lane == 0) {
                    __threadfence();
                    atomicAdd(&g_cnt[c * 32], 1u);
                }
            } else {
                __syncthreads();
                if (threadIdx.x == 0) {
                    __threadfence();
                    atomicAdd(&g_cnt[c * 32], 1u);
                }
            }
        }
        return;
    }

    // ===================== scan =====================
    const int swid = blockIdx.x * 4 + wid;       // 0..127
    const int ch   = swid & 1;                   // 0 = channel 1, 1 = channel 2
    const int b    = (swid >> 1) * 32 + lane;    // batch index

    float QCL, QCE, QWE, QWI, QCT, QWM;
    if (ch == 0) {
        QCL = 0.25f * (w[2] * (w[0] * w[1]));
        QCE = 0.25f * (w[0] * w[4]);
        QWE = 0.25f * w[5];
        QWI = 0.25f * w[6];
        QCT = 0.25f * (w[9] * w[8]);
        QWM = 0.25f * w[11];
    } else {
        QCL = 0.25f * (w[2] * (w[12] * w[13]));
        QCE = 0.25f * (w[12] * w[16]);
        QWE = 0.25f * w[17];
        QWI = 0.25f * w[18];
        QCT = 0.25f * (w[9] * w[20]);
        QWM = 0.25f * w[23];
    }
    const float QW3  = 0.25f * w[3];
    const float QW10 = 0.25f * w[10];

    float vL = -70.f, uL = -14.f, zL = 0.f;      // LLBN (b=.20,c=-65,d=6)
    float vE = -64.f, uE = -16.f;                // EBN  (b=.25,c=-55,d=.05)
    float vI = -64.f, uI = -16.f;                // IFN  (b=.25,c=-65,d=6)
    float vT = -70.f, uT = -14.f, zT = 0.f;      // TN   (b=.20,c=-50,d=2)
    float vM = -64.f, uM = -16.f;                // MN = IFN

    const size_t BT = (size_t)B_ * T_;
    float*  out_sA = out + (ch ? 2 * BT : 0)      + (size_t)b * T_;  // z6/z62
    float*  out_sB = out + (ch ? 3 * BT : 1 * BT) + (size_t)b * T_;  // vM/vM2
    float4* out_o4 = reinterpret_cast<float4*>(out + 4 * BT) + (size_t)b * T_;
    float4* out_v4 = reinterpret_cast<float4*>(out + 8 * BT) + (size_t)b * T_;

    int hc = 0;
    while (ld_acquire(&g_cnt[0]) < (unsigned)NBLK) __nanosleep(64);

    // Prefetch 8 timesteps ahead (two 4-step groups) to cover L2/DRAM latency.
    float cur[4], nx1[4];
    #pragma unroll
    for (int j = 0; j < 4; j++) cur[j] = g_S[j * B_ + b];
    #pragma unroll
    for (int j = 0; j < 4; j++) nx1[j] = g_S[(4 + j) * B_ + b];

    for (int t4 = 0; t4 < T_; t4 += 4) {
        int req = (t4 + 11) / CHUNK_T;
        if (req > NCHUNK - 1) req = NCHUNK - 1;
        if (req > hc) {                          // at most one poll per chunk
            while (ld_acquire(&g_cnt[req * 32]) < (unsigned)NBLK) __nanosleep(64);
            hc = req;
        }
        float nx2[4];
        #pragma unroll
        for (int j = 0; j < 4; j++) nx2[j] = g_S[(t4 + 8 + j) * B_ + b];

        float z6s[4], vMs[4];
        #pragma unroll
        for (int j = 0; j < 4; j++) {
            const float S = cur[j];

            float pL = izh_partial(vL, uL);
            float pE = izh_partial(vE, uE);
            float pI = izh_partial(vI, uI);
            float pT = izh_partial(vT, uT);
            float pM = izh_partial(vM, uM);

            float vnL = fmaf(QW3, zL, fmaf(QCL, S, pL));
            float z2  = izh_core(vL, uL, vnL, 0.20f, -65.f, 6.f);
            zL = z2;

            float vnE = fmaf(QWE, z2, fmaf(QCE, S, pE));
            float z3  = izh_core(vE, uE, vnE, 0.25f, -55.f, 0.05f);

            float vnI = fmaf(QWI, z3, pI);
            float z4  = izh_core(vI, uI, vnI, 0.25f, -65.f, 6.f);

            float vnT = fmaf(QCT, z3, fmaf(QW10, zT, pT));
            float z5  = izh_core(vT, uT, vnT, 0.20f, -50.f, 2.f);
            zT = z5;

            float vnM = fmaf(QWM, z5, pM);
            float z6  = izh_core(vM, uM, vnM, 0.25f, -65.f, 6.f);

            z6s[j] = z6;
            vMs[j] = vM;

            if (ch == 0) {                       // channel-1 warp emits 4-wide streams
                out_o4[t4 + j] = make_float4(z2, z3, z4, z5);
                out_v4[t4 + j] = make_float4(vL, vE, vI, vT);
            }
        }

        *reinterpret_cast<float4*>(out_sA + t4) =
            make_float4(z6s[0], z6s[1], z6s[2], z6s[3]);
        *reinterpret_cast<float4*>(out_sB + t4) =
            make_float4(vMs[0], vMs[1], vMs[2], vMs[3]);

        #pragma unroll
        for (int j = 0; j < 4; j++) { cur[j] = nx1[j]; nx1[j] = nx2[j]; }
    }
}

// ---------------------------------------------------------------------------
extern "C" void kernel_launch(void* const* d_in, const int* in_sizes, int n_in,
                              void* d_out, int out_size) {
    const float* inp = (const float*)d_in[0];
    const float* w   = (const float*)d_in[1];
    if (in_sizes[0] == 24) { const float* t = inp; inp = w; w = t; }

    init_kernel<<<1, 1024>>>();
    fused_kernel<<<NBLK, TPB>>>(inp, w, (float*)d_out);
}